// round 1
// baseline (speedup 1.0000x reference)
#include <cuda_runtime.h>
#include <math.h>

#define B_ROWS 4096
#define DIM    512
#define NCLS   31
#define NTOT   8192
#define NT     32        // 4096/128 tiles per side
#define TRI    528       // NT*(NT+1)/2

// ---------------- device scratch (no allocations allowed) ----------------
__device__ double g_sumsq;
__device__ double g_acc[3];          // ss, tt, st accumulators
__device__ float  g_S[DIM];          // column sums of concat(source,target)
__device__ float  g_sq[NTOT];        // row squared norms
__device__ int    g_scount[NCLS];
__device__ int    g_tcount[NCLS];
__device__ float  g_tcolsum[NCLS];
__device__ float  g_css[NCLS];       // scale*m/c^2
__device__ float  g_cst[NCLS];       // scale*m/c
__device__ float  g_invts[NCLS];     // m / t_colsum
__device__ float  g_u[B_ROWS * 32];  // masked normalized target logits (padded stride 32)
__device__ float  g_c[5];            // -log2(e)/(bw*2^i)
__device__ float  g_scale;
__device__ float  g_lamb;

// ---------------- init ----------------
__global__ void k_init() {
    int t = threadIdx.x;
    if (t == 0) g_sumsq = 0.0;
    if (t < 3) g_acc[t] = 0.0;
    if (t < NCLS) { g_scount[t] = 0; g_tcount[t] = 0; g_tcolsum[t] = 0.f; }
    if (t < DIM) g_S[t] = 0.f;
}

// ---------------- row squared norms (one warp per row) ----------------
__global__ void k_sq(const float* __restrict__ src, const float* __restrict__ tgt) {
    int w = (blockIdx.x * blockDim.x + threadIdx.x) >> 5;
    int lane = threadIdx.x & 31;
    if (w >= NTOT) return;
    const float* row = (w < B_ROWS) ? (src + (size_t)w * DIM)
                                    : (tgt + (size_t)(w - B_ROWS) * DIM);
    float s = 0.f;
    for (int k = lane; k < DIM; k += 32) { float v = row[k]; s = fmaf(v, v, s); }
    #pragma unroll
    for (int o = 16; o; o >>= 1) s += __shfl_xor_sync(0xffffffffu, s, o);
    if (lane == 0) { g_sq[w] = s; atomicAdd(&g_sumsq, (double)s); }
}

// ---------------- column sums of concat (for ||sum x||^2) ----------------
__global__ void k_colsum(const float* __restrict__ src, const float* __restrict__ tgt) {
    int d = threadIdx.x;   // 512 threads
    int b = blockIdx.x;    // 32 blocks, 128 rows each per array
    float s = 0.f;
    int r0 = b * 128;
    for (int r = r0; r < r0 + 128; r++) {
        s += src[(size_t)r * DIM + d] + tgt[(size_t)r * DIM + d];
    }
    atomicAdd(&g_S[d], s);
}

// ---------------- class stats ----------------
__global__ void k_stats(const int* __restrict__ lbl, const float* __restrict__ logits) {
    int b = blockIdx.x;           // 16 blocks x 256 threads
    int t = threadIdx.x;
    int i = b * 256 + t;
    atomicAdd(&g_scount[lbl[i]], 1);
    const float* row = logits + (size_t)i * NCLS;
    float mv = row[0]; int mi = 0;
    #pragma unroll
    for (int c = 1; c < NCLS; c++) { float v = row[c]; if (v > mv) { mv = v; mi = c; } }
    atomicAdd(&g_tcount[mi], 1);
    if (t < NCLS) {
        float s = 0.f;
        for (int r = 0; r < 256; r++) s += logits[(size_t)(b * 256 + r) * NCLS + t];
        atomicAdd(&g_tcolsum[t], s);
    }
}

// ---------------- finalize: m, scale, per-class coefs, bandwidth, lambda --------
__global__ void k_finalize(const int* __restrict__ curr_iter) {
    __shared__ double sred[512];
    __shared__ float  sm[NCLS];
    __shared__ float  sscale;
    int t = threadIdx.x;  // 512 threads
    double v = (double)g_S[t];
    sred[t] = v * v;
    __syncthreads();
    for (int o = 256; o; o >>= 1) { if (t < o) sred[t] += sred[t + o]; __syncthreads(); }
    if (t < NCLS) sm[t] = (g_scount[t] > 0 && g_tcount[t] > 0) ? 1.f : 0.f;
    __syncthreads();
    if (t == 0) {
        float cnt = 0.f;
        for (int c = 0; c < NCLS; c++) cnt += sm[c];
        sscale = (cnt > 0.f) ? 1.f / fmaxf(cnt, 1.f) : 0.f;
        g_scale = sscale;
    }
    __syncthreads();
    if (t < NCLS) {
        float m = sm[t];
        int sc = g_scount[t];
        float css = 0.f, cst = 0.f;
        if (sc > 0) { float fc = (float)sc; css = m * sscale / (fc * fc); cst = m * sscale / fc; }
        g_css[t] = css; g_cst[t] = cst;
        float ts = g_tcolsum[t]; if (ts == 0.f) ts = 100.f;
        g_invts[t] = m / ts;
    }
    if (t == 0) {
        double sumL2 = 2.0 * (double)NTOT * g_sumsq - 2.0 * sred[0];
        double bw = sumL2 / ((double)NTOT * (double)NTOT - (double)NTOT);
        bw = bw / 4.0;   // / KERNEL_MUL^(KERNEL_NUM/2)
        for (int i = 0; i < 5; i++)
            g_c[i] = (float)(-1.4426950408889634 / (bw * (double)(1 << i)));
        double p = (double)curr_iter[0] / 1000.0;
        g_lamb = (float)(2.0 / (1.0 + exp(-p)) - 1.0);
    }
}

// ---------------- masked normalized target logits ----------------
__global__ void k_u(const float* __restrict__ logits) {
    int i = blockIdx.x * blockDim.x + threadIdx.x;
    if (i >= B_ROWS) return;
    #pragma unroll
    for (int c = 0; c < NCLS; c++)
        g_u[i * 32 + c] = logits[(size_t)i * NCLS + c] * g_invts[c];
    g_u[i * 32 + 31] = 0.f;
}

__device__ __forceinline__ float ex2f(float x) {
    float r;
    asm("ex2.approx.ftz.f32 %0, %1;" : "=f"(r) : "f"(x));
    return r;
}

// ---------------- main fused GEMM + kernel-weight epilogue ----------------
__global__ __launch_bounds__(256, 2)
void k_main(const float* __restrict__ src, const float* __restrict__ tgt,
            const int* __restrict__ slabel) {
    __shared__ float As[8][128];
    __shared__ float Bs[8][128];
    __shared__ float sqI[128], sqJ[128];
    __shared__ float Ui[128][33];
    __shared__ float Uj[128][33];
    __shared__ int   Li[128];
    __shared__ int   Lj[128];
    __shared__ float s_css[NCLS], s_cst[NCLS];

    int bid = blockIdx.x;
    int type, ti, tj;
    if (bid < TRI) { type = 0; }
    else if (bid < 2 * TRI) { type = 1; bid -= TRI; }
    else { type = 2; bid -= 2 * TRI; }
    if (type < 2) {
        int r = 0, b = bid;
        while (b >= NT - r) { b -= NT - r; r++; }
        ti = r; tj = r + b;
    } else { ti = bid >> 5; tj = bid & 31; }

    const float* Xi = (type == 1) ? tgt : src;
    const float* Xj = (type == 0) ? src : tgt;
    int gi0 = ti * 128, gj0 = tj * 128;

    int t = threadIdx.x;
    int tx = t & 15, ty = t >> 4;
    int lr = t >> 1, lc = (t & 1) << 2;

    const float* Ai = Xi + (size_t)gi0 * DIM;
    const float* Bj = Xj + (size_t)gj0 * DIM;

    float acc[8][8];
    #pragma unroll
    for (int i = 0; i < 8; i++)
        #pragma unroll
        for (int j = 0; j < 8; j++) acc[i][j] = 0.f;

    for (int k0 = 0; k0 < DIM; k0 += 8) {
        float4 av = *(const float4*)(Ai + (size_t)lr * DIM + k0 + lc);
        float4 bv = *(const float4*)(Bj + (size_t)lr * DIM + k0 + lc);
        As[lc + 0][lr] = av.x; As[lc + 1][lr] = av.y;
        As[lc + 2][lr] = av.z; As[lc + 3][lr] = av.w;
        Bs[lc + 0][lr] = bv.x; Bs[lc + 1][lr] = bv.y;
        Bs[lc + 2][lr] = bv.z; Bs[lc + 3][lr] = bv.w;
        __syncthreads();
        #pragma unroll
        for (int kk = 0; kk < 8; kk++) {
            float a[8], b[8];
            #pragma unroll
            for (int i = 0; i < 8; i++) a[i] = As[kk][ty * 8 + i];
            #pragma unroll
            for (int j = 0; j < 8; j++) b[j] = Bs[kk][tx * 8 + j];
            #pragma unroll
            for (int i = 0; i < 8; i++)
                #pragma unroll
                for (int j = 0; j < 8; j++)
                    acc[i][j] = fmaf(a[i], b[j], acc[i][j]);
        }
        __syncthreads();
    }

    // ---- epilogue tables ----
    if (t < 128) {
        sqI[t] = g_sq[((type == 1) ? B_ROWS : 0) + gi0 + t];
        sqJ[t] = g_sq[((type == 0) ? 0 : B_ROWS) + gj0 + t];
    }
    if (type == 0 && t < 128) { Li[t] = slabel[gi0 + t]; Lj[t] = slabel[gj0 + t]; }
    if (type == 2 && t < 128) { Li[t] = slabel[gi0 + t]; }
    if (type != 0) {
        for (int idx = t; idx < 128 * 32; idx += 256) {
            int r = idx >> 5, c = idx & 31;
            Uj[r][c] = g_u[(size_t)(gj0 + r) * 32 + c];
        }
    }
    if (type == 1) {
        for (int idx = t; idx < 128 * 32; idx += 256) {
            int r = idx >> 5, c = idx & 31;
            Ui[r][c] = g_u[(size_t)(gi0 + r) * 32 + c];
        }
    }
    if (t < NCLS) { s_css[t] = g_css[t]; s_cst[t] = g_cst[t]; }
    float c0 = g_c[0], c1 = g_c[1], c2 = g_c[2], c3 = g_c[3], c4 = g_c[4];
    float scale = g_scale;
    __syncthreads();

    float part = 0.f;
    if (type == 0) {
        #pragma unroll
        for (int ii = 0; ii < 8; ii++) {
            int il = ty * 8 + ii;
            float si = sqI[il];
            int li = Li[il];
            float wcls = s_css[li];
            #pragma unroll
            for (int jj = 0; jj < 8; jj++) {
                int jl = tx * 8 + jj;
                float L2 = fmaxf(fmaf(-2.f, acc[ii][jj], si + sqJ[jl]), 0.f);
                float ks = ex2f(L2 * c0) + ex2f(L2 * c1) + ex2f(L2 * c2)
                         + ex2f(L2 * c3) + ex2f(L2 * c4);
                float w = (li == Lj[jl]) ? wcls : 0.f;
                part = fmaf(w, ks, part);
            }
        }
    } else if (type == 1) {
        #pragma unroll
        for (int ii = 0; ii < 8; ii++) {
            int il = ty * 8 + ii;
            float si = sqI[il];
            float ui[NCLS];
            #pragma unroll
            for (int c = 0; c < NCLS; c++) ui[c] = Ui[il][c];
            #pragma unroll
            for (int jj = 0; jj < 8; jj++) {
                int jl = tx * 8 + jj;
                float L2 = fmaxf(fmaf(-2.f, acc[ii][jj], si + sqJ[jl]), 0.f);
                float ks = ex2f(L2 * c0) + ex2f(L2 * c1) + ex2f(L2 * c2)
                         + ex2f(L2 * c3) + ex2f(L2 * c4);
                float ud = 0.f;
                #pragma unroll
                for (int c = 0; c < NCLS; c++) ud = fmaf(ui[c], Uj[jl][c], ud);
                part = fmaf(scale * ud, ks, part);
            }
        }
    } else {
        #pragma unroll
        for (int ii = 0; ii < 8; ii++) {
            int il = ty * 8 + ii;
            float si = sqI[il];
            int li = Li[il];
            float wc = s_cst[li];
            #pragma unroll
            for (int jj = 0; jj < 8; jj++) {
                int jl = tx * 8 + jj;
                float L2 = fmaxf(fmaf(-2.f, acc[ii][jj], si + sqJ[jl]), 0.f);
                float ks = ex2f(L2 * c0) + ex2f(L2 * c1) + ex2f(L2 * c2)
                         + ex2f(L2 * c3) + ex2f(L2 * c4);
                part = fmaf(wc * Uj[jl][li], ks, part);
            }
        }
    }

    #pragma unroll
    for (int o = 16; o; o >>= 1) part += __shfl_xor_sync(0xffffffffu, part, o);
    if ((t & 31) == 0) {
        double f = (type < 2 && ti != tj) ? 2.0 : 1.0;
        atomicAdd(&g_acc[type], f * (double)part);
    }
}

// ---------------- output ----------------
__global__ void k_out(float* out) {
    out[0] = (float)(g_lamb * (g_acc[0] + g_acc[1] - 2.0 * g_acc[2]));
}

extern "C" void kernel_launch(void* const* d_in, const int* in_sizes, int n_in,
                              void* d_out, int out_size) {
    const float* src    = (const float*)d_in[0];
    const float* tgt    = (const float*)d_in[1];
    const int*   lbl    = (const int*)d_in[2];
    const float* logits = (const float*)d_in[3];
    const int*   iter   = (const int*)d_in[4];
    float* out = (float*)d_out;

    k_init<<<1, 512>>>();
    k_sq<<<(NTOT * 32) / 256, 256>>>(src, tgt);
    k_colsum<<<32, 512>>>(src, tgt);
    k_stats<<<16, 256>>>(lbl, logits);
    k_finalize<<<1, 512>>>(iter);
    k_u<<<16, 256>>>(logits);
    k_main<<<2 * TRI + NT * NT, 256>>>(src, tgt, lbl);
    k_out<<<1, 1>>>(out);
}

// round 2
// speedup vs baseline: 1.3475x; 1.3475x over previous
#include <cuda_runtime.h>
#include <math.h>

#define B_ROWS 4096
#define DIM    512
#define NCLS   31
#define NTOT   8192
#define NT     32        // 4096/128 tiles per side
#define TRI    528       // NT*(NT+1)/2

typedef unsigned long long ull;

// ---------------- device scratch (no allocations allowed) ----------------
__device__ double g_sumsq;
__device__ double g_acc[3];          // ss, tt, st accumulators
__device__ float  g_S[DIM];          // column sums of concat(source,target)
__device__ float  g_sq[NTOT];        // row squared norms
__device__ int    g_scount[NCLS];
__device__ int    g_tcount[NCLS];
__device__ float  g_tcolsum[NCLS];
__device__ float  g_css[NCLS];       // scale*m/c^2
__device__ float  g_cst[NCLS];       // scale*m/c
__device__ float  g_invts[NCLS];     // m / t_colsum
__device__ float  g_u[B_ROWS * 32];  // masked normalized target logits (padded stride 32)
__device__ float  g_c[5];            // -log2(e)/(bw*2^i)
__device__ float  g_scale;
__device__ float  g_lamb;

// ---------------- init ----------------
__global__ void k_init() {
    int t = threadIdx.x;
    if (t == 0) g_sumsq = 0.0;
    if (t < 3) g_acc[t] = 0.0;
    if (t < NCLS) { g_scount[t] = 0; g_tcount[t] = 0; g_tcolsum[t] = 0.f; }
    if (t < DIM) g_S[t] = 0.f;
}

// ---------------- row squared norms (one warp per row) ----------------
__global__ void k_sq(const float* __restrict__ src, const float* __restrict__ tgt) {
    int w = (blockIdx.x * blockDim.x + threadIdx.x) >> 5;
    int lane = threadIdx.x & 31;
    if (w >= NTOT) return;
    const float* row = (w < B_ROWS) ? (src + (size_t)w * DIM)
                                    : (tgt + (size_t)(w - B_ROWS) * DIM);
    float s = 0.f;
    for (int k = lane; k < DIM; k += 32) { float v = row[k]; s = fmaf(v, v, s); }
    #pragma unroll
    for (int o = 16; o; o >>= 1) s += __shfl_xor_sync(0xffffffffu, s, o);
    if (lane == 0) { g_sq[w] = s; atomicAdd(&g_sumsq, (double)s); }
}

// ---------------- column sums of concat (for ||sum x||^2) ----------------
__global__ void k_colsum(const float* __restrict__ src, const float* __restrict__ tgt) {
    int d = threadIdx.x;   // 512 threads
    int b = blockIdx.x;    // 32 blocks, 128 rows each per array
    float s = 0.f;
    int r0 = b * 128;
    for (int r = r0; r < r0 + 128; r++) {
        s += src[(size_t)r * DIM + d] + tgt[(size_t)r * DIM + d];
    }
    atomicAdd(&g_S[d], s);
}

// ---------------- class stats ----------------
__global__ void k_stats(const int* __restrict__ lbl, const float* __restrict__ logits) {
    int b = blockIdx.x;           // 16 blocks x 256 threads
    int t = threadIdx.x;
    int i = b * 256 + t;
    atomicAdd(&g_scount[lbl[i]], 1);
    const float* row = logits + (size_t)i * NCLS;
    float mv = row[0]; int mi = 0;
    #pragma unroll
    for (int c = 1; c < NCLS; c++) { float v = row[c]; if (v > mv) { mv = v; mi = c; } }
    atomicAdd(&g_tcount[mi], 1);
    if (t < NCLS) {
        float s = 0.f;
        for (int r = 0; r < 256; r++) s += logits[(size_t)(b * 256 + r) * NCLS + t];
        atomicAdd(&g_tcolsum[t], s);
    }
}

// ---------------- finalize: m, scale, per-class coefs, bandwidth, lambda --------
__global__ void k_finalize(const int* __restrict__ curr_iter) {
    __shared__ double sred[512];
    __shared__ float  sm[NCLS];
    __shared__ float  sscale;
    int t = threadIdx.x;  // 512 threads
    double v = (double)g_S[t];
    sred[t] = v * v;
    __syncthreads();
    for (int o = 256; o; o >>= 1) { if (t < o) sred[t] += sred[t + o]; __syncthreads(); }
    if (t < NCLS) sm[t] = (g_scount[t] > 0 && g_tcount[t] > 0) ? 1.f : 0.f;
    __syncthreads();
    if (t == 0) {
        float cnt = 0.f;
        for (int c = 0; c < NCLS; c++) cnt += sm[c];
        sscale = (cnt > 0.f) ? 1.f / fmaxf(cnt, 1.f) : 0.f;
        g_scale = sscale;
    }
    __syncthreads();
    if (t < NCLS) {
        float m = sm[t];
        int sc = g_scount[t];
        float css = 0.f, cst = 0.f;
        if (sc > 0) { float fc = (float)sc; css = m * sscale / (fc * fc); cst = m * sscale / fc; }
        g_css[t] = css; g_cst[t] = cst;
        float ts = g_tcolsum[t]; if (ts == 0.f) ts = 100.f;
        g_invts[t] = m / ts;
    }
    if (t == 0) {
        double sumL2 = 2.0 * (double)NTOT * g_sumsq - 2.0 * sred[0];
        double bw = sumL2 / ((double)NTOT * (double)NTOT - (double)NTOT);
        bw = bw / 4.0;   // / KERNEL_MUL^(KERNEL_NUM/2)
        for (int i = 0; i < 5; i++)
            g_c[i] = (float)(-1.4426950408889634 / (bw * (double)(1 << i)));
        double p = (double)curr_iter[0] / 1000.0;
        g_lamb = (float)(2.0 / (1.0 + exp(-p)) - 1.0);
    }
}

// ---------------- masked normalized target logits ----------------
__global__ void k_u(const float* __restrict__ logits) {
    int i = blockIdx.x * blockDim.x + threadIdx.x;
    if (i >= B_ROWS) return;
    #pragma unroll
    for (int c = 0; c < NCLS; c++)
        g_u[i * 32 + c] = logits[(size_t)i * NCLS + c] * g_invts[c];
    g_u[i * 32 + 31] = 0.f;
}

__device__ __forceinline__ float ex2f(float x) {
    float r;
    asm("ex2.approx.ftz.f32 %0, %1;" : "=f"(r) : "f"(x));
    return r;
}

#define FFMA2(d, a, b) \
    asm("fma.rn.f32x2 %0, %1, %2, %0;" : "+l"(d) : "l"(a), "l"(b))

#define PACK2(d, x) \
    asm("mov.b64 %0, {%1, %1};" : "=l"(d) : "f"(x))

#define UNPACK2(lo, hi, v) \
    asm("mov.b64 {%0, %1}, %2;" : "=f"(lo), "=f"(hi) : "l"(v))

// ---------------- main fused GEMM + kernel-weight epilogue ----------------
__global__ __launch_bounds__(256, 2)
void k_main(const float* __restrict__ src, const float* __restrict__ tgt,
            const int* __restrict__ slabel) {
    __shared__ float As[8][128];
    __shared__ float Bs[8][128];
    __shared__ float sqI[128], sqJ[128];
    __shared__ float Ui[128][33];
    __shared__ float Uj[128][33];
    __shared__ int   Li[128];
    __shared__ int   Lj[128];
    __shared__ float s_css[NCLS], s_cst[NCLS];

    int bid = blockIdx.x;
    int type, ti, tj;
    if (bid < TRI) { type = 0; }
    else if (bid < 2 * TRI) { type = 1; bid -= TRI; }
    else { type = 2; bid -= 2 * TRI; }
    if (type < 2) {
        int r = 0, b = bid;
        while (b >= NT - r) { b -= NT - r; r++; }
        ti = r; tj = r + b;
    } else { ti = bid >> 5; tj = bid & 31; }

    const float* Xi = (type == 1) ? tgt : src;
    const float* Xj = (type == 0) ? src : tgt;
    int gi0 = ti * 128, gj0 = tj * 128;

    int t = threadIdx.x;
    int tx = t & 15, ty = t >> 4;
    int lr = t >> 1, lc = (t & 1) << 2;

    const float* Ai = Xi + (size_t)gi0 * DIM;
    const float* Bj = Xj + (size_t)gj0 * DIM;

    // packed accumulators: acc2[i][jp] holds columns (2*jp, 2*jp+1)
    ull acc2[8][4];
    #pragma unroll
    for (int i = 0; i < 8; i++)
        #pragma unroll
        for (int j = 0; j < 4; j++) acc2[i][j] = 0ull;

    for (int k0 = 0; k0 < DIM; k0 += 8) {
        float4 av = *(const float4*)(Ai + (size_t)lr * DIM + k0 + lc);
        float4 bv = *(const float4*)(Bj + (size_t)lr * DIM + k0 + lc);
        As[lc + 0][lr] = av.x; As[lc + 1][lr] = av.y;
        As[lc + 2][lr] = av.z; As[lc + 3][lr] = av.w;
        Bs[lc + 0][lr] = bv.x; Bs[lc + 1][lr] = bv.y;
        Bs[lc + 2][lr] = bv.z; Bs[lc + 3][lr] = bv.w;
        __syncthreads();
        #pragma unroll
        for (int kk = 0; kk < 8; kk++) {
            // b pairs: 4 x 64-bit loads (contiguous, 8B-aligned since tx*8*4B = 32B)
            ull bp[4];
            const ull* brow = (const ull*)&Bs[kk][tx * 8];
            #pragma unroll
            for (int jp = 0; jp < 4; jp++) bp[jp] = brow[jp];
            // a broadcast pairs
            ull aa[8];
            #pragma unroll
            for (int i = 0; i < 8; i++) {
                float avv = As[kk][ty * 8 + i];
                PACK2(aa[i], avv);
            }
            #pragma unroll
            for (int i = 0; i < 8; i++)
                #pragma unroll
                for (int jp = 0; jp < 4; jp++)
                    FFMA2(acc2[i][jp], aa[i], bp[jp]);
        }
        __syncthreads();
    }

    // unpack accumulators
    float acc[8][8];
    #pragma unroll
    for (int i = 0; i < 8; i++)
        #pragma unroll
        for (int jp = 0; jp < 4; jp++)
            UNPACK2(acc[i][2 * jp], acc[i][2 * jp + 1], acc2[i][jp]);

    // ---- epilogue tables ----
    if (t < 128) {
        sqI[t] = g_sq[((type == 1) ? B_ROWS : 0) + gi0 + t];
        sqJ[t] = g_sq[((type == 0) ? 0 : B_ROWS) + gj0 + t];
    }
    if (type == 0 && t < 128) { Li[t] = slabel[gi0 + t]; Lj[t] = slabel[gj0 + t]; }
    if (type == 2 && t < 128) { Li[t] = slabel[gi0 + t]; }
    if (type != 0) {
        for (int idx = t; idx < 128 * 32; idx += 256) {
            int r = idx >> 5, c = idx & 31;
            Uj[r][c] = g_u[(size_t)(gj0 + r) * 32 + c];
        }
    }
    if (type == 1) {
        for (int idx = t; idx < 128 * 32; idx += 256) {
            int r = idx >> 5, c = idx & 31;
            Ui[r][c] = g_u[(size_t)(gi0 + r) * 32 + c];
        }
    }
    if (t < NCLS) { s_css[t] = g_css[t]; s_cst[t] = g_cst[t]; }
    float c0 = g_c[0], c1 = g_c[1], c2 = g_c[2], c3 = g_c[3], c4 = g_c[4];
    float scale = g_scale;
    __syncthreads();

    float part = 0.f;
    if (type == 0) {
        #pragma unroll
        for (int ii = 0; ii < 8; ii++) {
            int il = ty * 8 + ii;
            float si = sqI[il];
            int li = Li[il];
            float wcls = s_css[li];
            #pragma unroll
            for (int jj = 0; jj < 8; jj++) {
                int jl = tx * 8 + jj;
                float L2 = fmaxf(fmaf(-2.f, acc[ii][jj], si + sqJ[jl]), 0.f);
                float ks = ex2f(L2 * c0) + ex2f(L2 * c1) + ex2f(L2 * c2)
                         + ex2f(L2 * c3) + ex2f(L2 * c4);
                float w = (li == Lj[jl]) ? wcls : 0.f;
                part = fmaf(w, ks, part);
            }
        }
    } else if (type == 1) {
        #pragma unroll
        for (int ii = 0; ii < 8; ii++) {
            int il = ty * 8 + ii;
            float si = sqI[il];
            float ui[NCLS];
            #pragma unroll
            for (int c = 0; c < NCLS; c++) ui[c] = Ui[il][c];
            #pragma unroll
            for (int jj = 0; jj < 8; jj++) {
                int jl = tx * 8 + jj;
                float L2 = fmaxf(fmaf(-2.f, acc[ii][jj], si + sqJ[jl]), 0.f);
                float ks = ex2f(L2 * c0) + ex2f(L2 * c1) + ex2f(L2 * c2)
                         + ex2f(L2 * c3) + ex2f(L2 * c4);
                float ud = 0.f;
                #pragma unroll
                for (int c = 0; c < NCLS; c++) ud = fmaf(ui[c], Uj[jl][c], ud);
                part = fmaf(scale * ud, ks, part);
            }
        }
    } else {
        #pragma unroll
        for (int ii = 0; ii < 8; ii++) {
            int il = ty * 8 + ii;
            float si = sqI[il];
            int li = Li[il];
            float wc = s_cst[li];
            #pragma unroll
            for (int jj = 0; jj < 8; jj++) {
                int jl = tx * 8 + jj;
                float L2 = fmaxf(fmaf(-2.f, acc[ii][jj], si + sqJ[jl]), 0.f);
                float ks = ex2f(L2 * c0) + ex2f(L2 * c1) + ex2f(L2 * c2)
                         + ex2f(L2 * c3) + ex2f(L2 * c4);
                part = fmaf(wc * Uj[jl][li], ks, part);
            }
        }
    }

    #pragma unroll
    for (int o = 16; o; o >>= 1) part += __shfl_xor_sync(0xffffffffu, part, o);
    if ((t & 31) == 0) {
        double f = (type < 2 && ti != tj) ? 2.0 : 1.0;
        atomicAdd(&g_acc[type], f * (double)part);
    }
}

// ---------------- output ----------------
__global__ void k_out(float* out) {
    out[0] = (float)(g_lamb * (g_acc[0] + g_acc[1] - 2.0 * g_acc[2]));
}

extern "C" void kernel_launch(void* const* d_in, const int* in_sizes, int n_in,
                              void* d_out, int out_size) {
    const float* src    = (const float*)d_in[0];
    const float* tgt    = (const float*)d_in[1];
    const int*   lbl    = (const int*)d_in[2];
    const float* logits = (const float*)d_in[3];
    const int*   iter   = (const int*)d_in[4];
    float* out = (float*)d_out;

    k_init<<<1, 512>>>();
    k_sq<<<(NTOT * 32) / 256, 256>>>(src, tgt);
    k_colsum<<<32, 512>>>(src, tgt);
    k_stats<<<16, 256>>>(lbl, logits);
    k_finalize<<<1, 512>>>(iter);
    k_u<<<16, 256>>>(logits);
    k_main<<<2 * TRI + NT * NT, 256>>>(src, tgt, lbl);
    k_out<<<1, 1>>>(out);
}

// round 6
// speedup vs baseline: 1.5639x; 1.1606x over previous
#include <cuda_runtime.h>
#include <math.h>
#include <stdint.h>

#define B_ROWS 4096
#define DIM    512
#define NCLS   31
#define NTOT   8192
#define NT     32        // 4096/128 tiles per side
#define TRI    528       // NT*(NT+1)/2

typedef unsigned long long ull;

// ---------------- device scratch ----------------
__device__ double g_sumsq;
__device__ double g_acc[3];
__device__ float  g_S[DIM];
__device__ float  g_sq[NTOT];
__device__ int    g_scount[NCLS];
__device__ int    g_tcount[NCLS];
__device__ float  g_tcolsum[NCLS];
__device__ float  g_css[NCLS];
__device__ float  g_cst[NCLS];
__device__ float  g_invts[NCLS];
__device__ __align__(16) float g_u[B_ROWS * 32];
__device__ float  g_c[5];
__device__ float  g_scale;
__device__ float  g_lamb;
// precomputed TT weights (scale * <u_i,u_j>), upper-triangle tiles, [tri][128][128]
__device__ __align__(16) float g_wtt[TRI * 128 * 128];

// ---------------- init ----------------
__global__ void k_init() {
    int t = threadIdx.x;
    if (t == 0) g_sumsq = 0.0;
    if (t < 3) g_acc[t] = 0.0;
    if (t < NCLS) { g_scount[t] = 0; g_tcount[t] = 0; g_tcolsum[t] = 0.f; }
    if (t < DIM) g_S[t] = 0.f;
}

// ---------------- row squared norms ----------------
__global__ void k_sq(const float* __restrict__ src, const float* __restrict__ tgt) {
    int w = (blockIdx.x * blockDim.x + threadIdx.x) >> 5;
    int lane = threadIdx.x & 31;
    if (w >= NTOT) return;
    const float* row = (w < B_ROWS) ? (src + (size_t)w * DIM)
                                    : (tgt + (size_t)(w - B_ROWS) * DIM);
    float s = 0.f;
    for (int k = lane; k < DIM; k += 32) { float v = row[k]; s = fmaf(v, v, s); }
    #pragma unroll
    for (int o = 16; o; o >>= 1) s += __shfl_xor_sync(0xffffffffu, s, o);
    if (lane == 0) { g_sq[w] = s; atomicAdd(&g_sumsq, (double)s); }
}

// ---------------- column sums ----------------
__global__ void k_colsum(const float* __restrict__ src, const float* __restrict__ tgt) {
    int d = threadIdx.x;
    int b = blockIdx.x;
    float s = 0.f;
    int r0 = b * 128;
    for (int r = r0; r < r0 + 128; r++)
        s += src[(size_t)r * DIM + d] + tgt[(size_t)r * DIM + d];
    atomicAdd(&g_S[d], s);
}

// ---------------- class stats ----------------
__global__ void k_stats(const int* __restrict__ lbl, const float* __restrict__ logits) {
    int b = blockIdx.x;
    int t = threadIdx.x;
    int i = b * 256 + t;
    atomicAdd(&g_scount[lbl[i]], 1);
    const float* row = logits + (size_t)i * NCLS;
    float mv = row[0]; int mi = 0;
    #pragma unroll
    for (int c = 1; c < NCLS; c++) { float v = row[c]; if (v > mv) { mv = v; mi = c; } }
    atomicAdd(&g_tcount[mi], 1);
    if (t < NCLS) {
        float s = 0.f;
        for (int r = 0; r < 256; r++) s += logits[(size_t)(b * 256 + r) * NCLS + t];
        atomicAdd(&g_tcolsum[t], s);
    }
}

// ---------------- finalize ----------------
__global__ void k_finalize(const int* __restrict__ curr_iter) {
    __shared__ double sred[512];
    __shared__ float  sm[NCLS];
    __shared__ float  sscale;
    int t = threadIdx.x;
    double v = (double)g_S[t];
    sred[t] = v * v;
    __syncthreads();
    for (int o = 256; o; o >>= 1) { if (t < o) sred[t] += sred[t + o]; __syncthreads(); }
    if (t < NCLS) sm[t] = (g_scount[t] > 0 && g_tcount[t] > 0) ? 1.f : 0.f;
    __syncthreads();
    if (t == 0) {
        float cnt = 0.f;
        for (int c = 0; c < NCLS; c++) cnt += sm[c];
        sscale = (cnt > 0.f) ? 1.f / fmaxf(cnt, 1.f) : 0.f;
        g_scale = sscale;
    }
    __syncthreads();
    if (t < NCLS) {
        float m = sm[t];
        int sc = g_scount[t];
        float css = 0.f, cst = 0.f;
        if (sc > 0) { float fc = (float)sc; css = m * sscale / (fc * fc); cst = m * sscale / fc; }
        g_css[t] = css; g_cst[t] = cst;
        float ts = g_tcolsum[t]; if (ts == 0.f) ts = 100.f;
        g_invts[t] = m / ts;
    }
    if (t == 0) {
        double sumL2 = 2.0 * (double)NTOT * g_sumsq - 2.0 * sred[0];
        double bw = sumL2 / ((double)NTOT * (double)NTOT - (double)NTOT);
        bw = bw / 4.0;
        for (int i = 0; i < 5; i++)
            g_c[i] = (float)(-1.4426950408889634 / (bw * (double)(1 << i)));
        double p = (double)curr_iter[0] / 1000.0;
        g_lamb = (float)(2.0 / (1.0 + exp(-p)) - 1.0);
    }
}

// ---------------- masked normalized target logits ----------------
__global__ void k_u(const float* __restrict__ logits) {
    int i = blockIdx.x * blockDim.x + threadIdx.x;
    if (i >= B_ROWS) return;
    #pragma unroll
    for (int c = 0; c < NCLS; c++)
        g_u[i * 32 + c] = logits[(size_t)i * NCLS + c] * g_invts[c];
    g_u[i * 32 + 31] = 0.f;
}

// ---------------- precompute TT weight tiles: scale * U U^T ----------------
__global__ __launch_bounds__(256, 2)
void k_wtt() {
    __shared__ float Us[128][33];
    __shared__ float Ut[128][33];
    int bid = blockIdx.x;     // tri index
    int r = 0, b = bid;
    while (b >= NT - r) { b -= NT - r; r++; }
    int ti = r, tj = r + b;
    int gi0 = ti * 128, gj0 = tj * 128;
    int t = threadIdx.x;
    int tx = t & 15, ty = t >> 4;

    // load U tiles (g_u rows are 32 floats, stride 32)
    for (int idx = t; idx < 4096; idx += 256) {
        int row = idx >> 5, c = idx & 31;
        Us[row][c] = g_u[(size_t)(gi0 + row) * 32 + c];
        Ut[row][c] = g_u[(size_t)(gj0 + row) * 32 + c];
    }
    __syncthreads();

    float acc[8][8];
    #pragma unroll
    for (int i = 0; i < 8; i++)
        #pragma unroll
        for (int j = 0; j < 8; j++) acc[i][j] = 0.f;

    #pragma unroll 1
    for (int c = 0; c < NCLS; c++) {
        float a[8], bb[8];
        #pragma unroll
        for (int i = 0; i < 8; i++) a[i] = Us[ty * 8 + i][c];
        #pragma unroll
        for (int j = 0; j < 8; j++) bb[j] = Ut[tx * 8 + j][c];
        #pragma unroll
        for (int i = 0; i < 8; i++)
            #pragma unroll
            for (int j = 0; j < 8; j++)
                acc[i][j] = fmaf(a[i], bb[j], acc[i][j]);
    }

    float scale = g_scale;
    float* W = g_wtt + (size_t)bid * 16384;
    #pragma unroll
    for (int i = 0; i < 8; i++) {
        int il = ty * 8 + i;
        float4 v0 = make_float4(acc[i][0]*scale, acc[i][1]*scale, acc[i][2]*scale, acc[i][3]*scale);
        float4 v1 = make_float4(acc[i][4]*scale, acc[i][5]*scale, acc[i][6]*scale, acc[i][7]*scale);
        *(float4*)(W + il * 128 + tx * 8 + 0) = v0;
        *(float4*)(W + il * 128 + tx * 8 + 4) = v1;
    }
}

// ---------------- helpers ----------------
__device__ __forceinline__ float ex2f(float x) {
    float r; asm("ex2.approx.ftz.f32 %0, %1;" : "=f"(r) : "f"(x)); return r;
}
#define FFMA2(d, a, b) \
    asm("fma.rn.f32x2 %0, %1, %2, %0;" : "+l"(d) : "l"(a), "l"(b))
#define PACK2(d, x) \
    asm("mov.b64 %0, {%1, %1};" : "=l"(d) : "f"(x))
#define UNPACK2(lo, hi, v) \
    asm("mov.b64 {%0, %1}, %2;" : "=f"(lo), "=f"(hi) : "l"(v))

// ---------------- main fused GEMM + kernel-weight epilogue ----------------
__global__ __launch_bounds__(256, 2)
void k_main(const float* __restrict__ src, const float* __restrict__ tgt,
            const int* __restrict__ slabel) {
    __shared__ float As[2][8][128];     // [stage][k][row]
    __shared__ float BP[2][8][128];     // pair-swizzled: ull idx = kk*64 + jp*16 + tx
    __shared__ float sqI[128], sqJ[128];
    __shared__ int   Li[128], Lj[128];
    __shared__ float s_css[32], s_cst[32];
    __shared__ float UjT[32][128];      // type==2 only: [class][j]

    int bid = blockIdx.x;
    int type, ti, tj, triq = 0;
    if (bid < TRI) { type = 0; }
    else if (bid < 2 * TRI) { type = 1; bid -= TRI; }
    else { type = 2; bid -= 2 * TRI; }
    if (type < 2) {
        int r = 0, b = bid;
        while (b >= NT - r) { b -= NT - r; r++; }
        ti = r; tj = r + b; triq = bid;
    } else { ti = bid >> 5; tj = bid & 31; }

    const float* Xi = (type == 1) ? tgt : src;
    const float* Xj = (type == 0) ? src : tgt;
    int gi0 = ti * 128, gj0 = tj * 128;

    int t = threadIdx.x;
    int tx = t & 15, ty = t >> 4;
    int lr = t >> 1, lc = (t & 1) << 2;

    const float* pa = Xi + (size_t)(gi0 + lr) * DIM + lc;
    const float* pb = Xj + (size_t)(gj0 + lr) * DIM + lc;

    // pair-swizzle store index for B (depends only on lr)
    int pi_ = lr >> 1;
    int bfi = ((pi_ & 3) * 16 + (pi_ >> 2)) * 2 + (lr & 1);

    // ---- small-table loads (independent of stages) ----
    if (t < 128) {
        sqI[t] = g_sq[((type == 1) ? B_ROWS : 0) + gi0 + t];
        sqJ[t] = g_sq[((type == 0) ? 0 : B_ROWS) + gj0 + t];
        if (type != 1) Li[t] = slabel[gi0 + t];
        if (type == 0) Lj[t] = slabel[gj0 + t];
    }
    if (t < NCLS) { s_css[t] = g_css[t]; s_cst[t] = g_cst[t]; }
    if (type == 2) {
        for (int idx = t; idx < 4096; idx += 256) {
            int c = idx >> 7, j = idx & 127;
            UjT[c][j] = g_u[(size_t)(gj0 + j) * 32 + c];
        }
    }

    // ---- prefetch first chunk ----
    float4 a_nx = *(const float4*)pa;
    float4 b_nx = *(const float4*)pb;

    ull acc2[8][4];
    #pragma unroll
    for (int i = 0; i < 8; i++)
        #pragma unroll
        for (int j = 0; j < 4; j++) acc2[i][j] = 0ull;

    #pragma unroll 1
    for (int c = 0; c < 64; c++) {
        int s = c & 1;
        // store current chunk
        As[s][lc + 0][lr] = a_nx.x; As[s][lc + 1][lr] = a_nx.y;
        As[s][lc + 2][lr] = a_nx.z; As[s][lc + 3][lr] = a_nx.w;
        BP[s][lc + 0][bfi] = b_nx.x; BP[s][lc + 1][bfi] = b_nx.y;
        BP[s][lc + 2][bfi] = b_nx.z; BP[s][lc + 3][bfi] = b_nx.w;
        __syncthreads();
        // prefetch next chunk (latency hidden under compute)
        if (c < 63) {
            a_nx = *(const float4*)(pa + (c + 1) * 8);
            b_nx = *(const float4*)(pb + (c + 1) * 8);
        }
        #pragma unroll
        for (int kk = 0; kk < 8; kk++) {
            const ull* brow = (const ull*)&BP[s][kk][0];
            ull bp[4];
            #pragma unroll
            for (int jp = 0; jp < 4; jp++) bp[jp] = brow[jp * 16 + tx];
            ull aa[8];
            #pragma unroll
            for (int i = 0; i < 8; i++) {
                float av = As[s][kk][ty * 8 + i];
                PACK2(aa[i], av);
            }
            #pragma unroll
            for (int i = 0; i < 8; i++)
                #pragma unroll
                for (int jp = 0; jp < 4; jp++)
                    FFMA2(acc2[i][jp], aa[i], bp[jp]);
        }
        __syncthreads();
    }

    // ---- epilogue ----
    float c4 = g_c[4];
    float part = 0.f;

    if (type == 0) {
        #pragma unroll
        for (int ii = 0; ii < 8; ii++) {
            int il = ty * 8 + ii;
            float si = sqI[il];
            int li = Li[il];
            float wcls = s_css[li];
            #pragma unroll
            for (int jp = 0; jp < 4; jp++) {
                float d0, d1;
                UNPACK2(d0, d1, acc2[ii][jp]);
                #pragma unroll
                for (int h = 0; h < 2; h++) {
                    int jl = tx * 8 + 2 * jp + h;
                    float dot = h ? d1 : d0;
                    float L2 = fmaxf(fmaf(-2.f, dot, si + sqJ[jl]), 0.f);
                    float e4 = ex2f(L2 * c4);
                    float e3 = e4 * e4, e2 = e3 * e3, e1 = e2 * e2, e0 = e1 * e1;
                    float ks = ((e0 + e1) + (e2 + e3)) + e4;
                    float w = (li == Lj[jl]) ? wcls : 0.f;
                    part = fmaf(w, ks, part);
                }
            }
        }
    } else if (type == 1) {
        const float4* Wt = (const float4*)(g_wtt + (size_t)triq * 16384);
        int base = (ty * 8) * 32 + tx * 2;  // float4 units: row il -> il*32
        float4 wa = Wt[base], wb = Wt[base + 1];
        #pragma unroll
        for (int ii = 0; ii < 8; ii++) {
            int il = ty * 8 + ii;
            float si = sqI[il];
            float wv[8] = { wa.x, wa.y, wa.z, wa.w, wb.x, wb.y, wb.z, wb.w };
            if (ii < 7) { wa = Wt[base + (ii + 1) * 32]; wb = Wt[base + (ii + 1) * 32 + 1]; }
            #pragma unroll
            for (int jp = 0; jp < 4; jp++) {
                float d0, d1;
                UNPACK2(d0, d1, acc2[ii][jp]);
                #pragma unroll
                for (int h = 0; h < 2; h++) {
                    int jj = 2 * jp + h;
                    int jl = tx * 8 + jj;
                    float dot = h ? d1 : d0;
                    float L2 = fmaxf(fmaf(-2.f, dot, si + sqJ[jl]), 0.f);
                    float e4 = ex2f(L2 * c4);
                    float e3 = e4 * e4, e2 = e3 * e3, e1 = e2 * e2, e0 = e1 * e1;
                    float ks = ((e0 + e1) + (e2 + e3)) + e4;
                    part = fmaf(wv[jj], ks, part);
                }
            }
        }
    } else {
        #pragma unroll
        for (int ii = 0; ii < 8; ii++) {
            int il = ty * 8 + ii;
            float si = sqI[il];
            int li = Li[il];
            float wc = s_cst[li];
            #pragma unroll
            for (int jp = 0; jp < 4; jp++) {
                float d0, d1;
                UNPACK2(d0, d1, acc2[ii][jp]);
                #pragma unroll
                for (int h = 0; h < 2; h++) {
                    int jl = tx * 8 + 2 * jp + h;
                    float dot = h ? d1 : d0;
                    float L2 = fmaxf(fmaf(-2.f, dot, si + sqJ[jl]), 0.f);
                    float e4 = ex2f(L2 * c4);
                    float e3 = e4 * e4, e2 = e3 * e3, e1 = e2 * e2, e0 = e1 * e1;
                    float ks = ((e0 + e1) + (e2 + e3)) + e4;
                    part = fmaf(wc * UjT[li][jl], ks, part);
                }
            }
        }
    }

    #pragma unroll
    for (int o = 16; o; o >>= 1) part += __shfl_xor_sync(0xffffffffu, part, o);
    if ((t & 31) == 0) {
        double f = (type < 2 && ti != tj) ? 2.0 : 1.0;
        atomicAdd(&g_acc[type], f * (double)part);
    }
}

// ---------------- output ----------------
__global__ void k_out(float* out) {
    out[0] = (float)(g_lamb * (g_acc[0] + g_acc[1] - 2.0 * g_acc[2]));
}

extern "C" void kernel_launch(void* const* d_in, const int* in_sizes, int n_in,
                              void* d_out, int out_size) {
    const float* src    = (const float*)d_in[0];
    const float* tgt    = (const float*)d_in[1];
    const int*   lbl    = (const int*)d_in[2];
    const float* logits = (const float*)d_in[3];
    const int*   iter   = (const int*)d_in[4];
    float* out = (float*)d_out;

    k_init<<<1, 512>>>();
    k_sq<<<(NTOT * 32) / 256, 256>>>(src, tgt);
    k_colsum<<<32, 512>>>(src, tgt);
    k_stats<<<16, 256>>>(lbl, logits);
    k_finalize<<<1, 512>>>(iter);
    k_u<<<16, 256>>>(logits);
    k_wtt<<<TRI, 256>>>();
    k_main<<<2 * TRI + NT * NT, 256>>>(src, tgt, lbl);
    k_out<<<1, 1>>>(out);
}